// round 4
// baseline (speedup 1.0000x reference)
#include <cuda_runtime.h>
#include <cuda_bf16.h>
#include <cstdint>

// Problem shape (fixed)
#define MDIM 512            // reduction dim
#define KDIM 256            // output cols (w rows)
#define MROWS 2048          // output rows (B*N)
#define TOTROWS (MROWS + KDIM)

// GEMM tiling: int8, full-K resident
#define BM 64
#define BN 64
#define LDSB 528            // smem row stride in BYTES (512 + 16): conflict-free ldmatrix
#define SMEM_ROWS (BM + BN) // 128
#define SMEM_BYTES (SMEM_ROWS * LDSB)   // 67584

// Scratch (int8 quantized operands)
__device__ __align__(16) int8_t g_xq[MROWS * MDIM];   // 1 MB
__device__ __align__(16) int8_t g_wq[KDIM * MDIM];    // 128 KB
__device__ float g_rowsum[MROWS];
__device__ float g_colsum[KDIM];

// ---------------------------------------------------------------------------
// quantize: q = clip(rint(v/s + zp), -128, 127)
// ---------------------------------------------------------------------------
__device__ __forceinline__ float quantize1(float v, float s, float zp) {
    float q = rintf(__fadd_rn(__fdiv_rn(v, s), zp));
    return fminf(fmaxf(q, -128.0f), 127.0f);
}

// Fused quantize: rows [0,2048)=x, [2048,2304)=w. 2 rows/block, 4 warps/row.
__global__ __launch_bounds__(256)
void quant_all_kernel(const float* __restrict__ x,
                      const float* __restrict__ w,
                      const float* __restrict__ xs_p, const float* __restrict__ xzp_p,
                      const float* __restrict__ ws_p, const float* __restrict__ wzp_p) {
    __shared__ float spart[8];
    const int tid  = threadIdx.x;
    const int lane = tid & 31;
    const int wid  = tid >> 5;
    const int row  = blockIdx.x * 2 + (tid >> 7);
    const int q4   = ((tid >> 5) & 3) * 32 + lane;   // float4 index in row (0..127)

    const bool isX = row < MROWS;
    const float s  = isX ? xs_p[0]  : ws_p[0];
    const float zp = isX ? xzp_p[0] : wzp_p[0];
    const float* src = isX ? (x + (size_t)row * MDIM)
                           : (w + (size_t)(row - MROWS) * MDIM);
    int8_t* dst = isX ? (g_xq + (size_t)row * MDIM)
                      : (g_wq + (size_t)(row - MROWS) * MDIM);

    float4 v = reinterpret_cast<const float4*>(src)[q4];
    float q0 = quantize1(v.x, s, zp);
    float q1 = quantize1(v.y, s, zp);
    float q2 = quantize1(v.z, s, zp);
    float q3 = quantize1(v.w, s, zp);

    int i0 = __float2int_rn(q0);
    int i1 = __float2int_rn(q1);
    int i2 = __float2int_rn(q2);
    int i3 = __float2int_rn(q3);
    uint32_t packed = (uint32_t)(i0 & 0xFF) | ((uint32_t)(i1 & 0xFF) << 8) |
                      ((uint32_t)(i2 & 0xFF) << 16) | ((uint32_t)i3 << 24);
    reinterpret_cast<uint32_t*>(dst)[q4] = packed;

    float sum = q0 + q1 + q2 + q3;
#pragma unroll
    for (int off = 16; off > 0; off >>= 1)
        sum += __shfl_xor_sync(0xFFFFFFFFu, sum, off);
    if (lane == 0) spart[wid] = sum;
    __syncthreads();
    if (tid < 2) {
        int r = blockIdx.x * 2 + tid;
        float total = spart[tid * 4 + 0] + spart[tid * 4 + 1] +
                      spart[tid * 4 + 2] + spart[tid * 4 + 3];
        if (r < MROWS) g_rowsum[r] = total;
        else           g_colsum[r - MROWS] = total;
    }
    // PDL: allow dependent GEMM grid to launch; prior stores are visible to it.
    asm volatile("griddepcontrol.launch_dependents;" ::: "memory");
}

// ---------------------------------------------------------------------------
// GEMM helpers
// ---------------------------------------------------------------------------
__device__ __forceinline__ uint32_t smem_u32(const void* p) {
    return (uint32_t)__cvta_generic_to_shared(p);
}
__device__ __forceinline__ void cp_async16(uint32_t saddr, const void* gptr) {
    asm volatile("cp.async.cg.shared.global [%0], [%1], 16;\n"
                 :: "r"(saddr), "l"(gptr));
}
__device__ __forceinline__ void cp_commit() {
    asm volatile("cp.async.commit_group;\n");
}
template <int N>
__device__ __forceinline__ void cp_wait() {
    asm volatile("cp.async.wait_group %0;\n" :: "n"(N));
}
__device__ __forceinline__ void ldsm_x4(uint32_t& r0, uint32_t& r1,
                                        uint32_t& r2, uint32_t& r3, uint32_t addr) {
    asm volatile("ldmatrix.sync.aligned.m8n8.x4.shared.b16 {%0,%1,%2,%3}, [%4];"
                 : "=r"(r0), "=r"(r1), "=r"(r2), "=r"(r3) : "r"(addr));
}
// int8 IMMA: D(s32) = A(s8,16x32) * B(s8,32x8) + C
__device__ __forceinline__ void imma16832(int& c0, int& c1, int& c2, int& c3,
                                          uint32_t a0, uint32_t a1, uint32_t a2, uint32_t a3,
                                          uint32_t b0, uint32_t b1) {
    asm volatile(
        "mma.sync.aligned.m16n8k32.row.col.s32.s8.s8.s32 "
        "{%0,%1,%2,%3}, {%4,%5,%6,%7}, {%8,%9}, {%0,%1,%2,%3};"
        : "+r"(c0), "+r"(c1), "+r"(c2), "+r"(c3)
        : "r"(a0), "r"(a1), "r"(a2), "r"(a3), "r"(b0), "r"(b1));
}

// ---------------------------------------------------------------------------
// Full-K-resident int8 GEMM. 512 threads (16 warps, 4m x 4n), warp tile 16x16.
// All loads issued in 4 K-slice commit groups; incremental waits.
// ---------------------------------------------------------------------------
__global__ __launch_bounds__(512, 1)
void lut_gemm_kernel(float* __restrict__ out,
                     const float* __restrict__ xs_p, const float* __restrict__ xzp_p,
                     const float* __restrict__ ws_p, const float* __restrict__ wzp_p) {
    extern __shared__ int8_t smem[];   // SMEM_ROWS x LDSB bytes

    // PDL: wait for quant grid's memory before touching g_xq/g_wq.
    asm volatile("griddepcontrol.wait;" ::: "memory");

    const int tid  = threadIdx.x;
    const int lane = tid & 31;
    const int warp = tid >> 5;
    const int wm = warp >> 2;       // 0..3 (16 rows each)
    const int wn = warp & 3;        // 0..3 (16 cols each)

    const int m0 = blockIdx.x * BM;
    const int n0 = blockIdx.y * BN;

    // ---- issue all loads: 4 groups, one per 128-elem K slice ----
    // Per group: 128 rows x 8 chunks(16B) = 1024 chunks = 2 per thread.
#pragma unroll
    for (int g = 0; g < 4; g++) {
#pragma unroll
        for (int i = 0; i < 2; i++) {
            int idx = tid + i * 512;          // 0..1023
            int rr  = idx >> 3;               // 0..127
            int cb  = g * 128 + (idx & 7) * 16;  // byte offset in row
            const int8_t* src = (rr < BM)
                ? (g_xq + (size_t)(m0 + rr) * MDIM + cb)
                : (g_wq + (size_t)(n0 + rr - BM) * MDIM + cb);
            cp_async16(smem_u32(&smem[rr * LDSB + cb]), src);
        }
        cp_commit();
    }

    int acc[2][4];
#pragma unroll
    for (int nb = 0; nb < 2; nb++)
#pragma unroll
        for (int q = 0; q < 4; q++) acc[nb][q] = 0;

    const uint32_t sbase = smem_u32(smem);
    // A frag (m16 x k32) address per lane: tile t=lane>>3:
    //   t0: row (lane&7),   k+0 ; t1: row+8, k+0 ; t2: row, k+16 ; t3: row+8, k+16
    const int a_r = wm * 16 + (lane & 7) + ((lane >> 3) & 1) * 8;
    const int a_k = (lane >> 4) * 16;
    // B frag (n16 x k32): t0: n(lane&7) k+0 ; t1: n k+16 ; t2: n+8 k+0 ; t3: n+8 k+16
    const int b_r = BM + wn * 16 + (lane & 7) + (lane >> 4) * 8;
    const int b_k = ((lane >> 3) & 1) * 16;

#pragma unroll
    for (int g = 0; g < 4; g++) {
        switch (g) {
            case 0: cp_wait<3>(); break;
            case 1: cp_wait<2>(); break;
            case 2: cp_wait<1>(); break;
            default: cp_wait<0>(); break;
        }
        __syncthreads();

#pragma unroll
        for (int ks = 0; ks < 4; ks++) {
            const int kk = g * 128 + ks * 32;
            uint32_t a0, a1, a2, a3, b0, b1, b2, b3;
            ldsm_x4(a0, a1, a2, a3, sbase + a_r * LDSB + kk + a_k);
            ldsm_x4(b0, b1, b2, b3, sbase + b_r * LDSB + kk + b_k);
            imma16832(acc[0][0], acc[0][1], acc[0][2], acc[0][3],
                      a0, a1, a2, a3, b0, b1);
            imma16832(acc[1][0], acc[1][1], acc[1][2], acc[1][3],
                      a0, a1, a2, a3, b2, b3);
        }
    }

    // ---- epilogue: zero-point corrections + rescale (exact in fp32) ----
    const float xs  = xs_p[0];
    const float xzp = xzp_p[0];
    const float ws  = ws_p[0];
    const float wzp = wzp_p[0];
    const float sc  = xs * ws;
    const float kconst = (float)MDIM * xzp * wzp;

#pragma unroll
    for (int nb = 0; nb < 2; nb++) {
        int col = n0 + wn * 16 + nb * 8 + (lane & 3) * 2;
        float cs0 = g_colsum[col];
        float cs1 = g_colsum[col + 1];
#pragma unroll
        for (int half = 0; half < 2; half++) {
            int row = m0 + wm * 16 + (lane >> 2) + half * 8;
            float rs = g_rowsum[row];
            float corr = kconst - wzp * rs;
            float v0 = (__int2float_rn(acc[nb][half * 2 + 0]) + corr - xzp * cs0) * sc;
            float v1 = (__int2float_rn(acc[nb][half * 2 + 1]) + corr - xzp * cs1) * sc;
            *reinterpret_cast<float2*>(out + (size_t)row * KDIM + col) =
                make_float2(v0, v1);
        }
    }
}

// ---------------------------------------------------------------------------
// Launch. Inputs: x, w, lut, x_scale, x_zero_point, w_scale, w_zero_point.
// ---------------------------------------------------------------------------
extern "C" void kernel_launch(void* const* d_in, const int* in_sizes, int n_in,
                              void* d_out, int out_size) {
    const float* x   = (const float*)d_in[0];
    const float* w   = (const float*)d_in[1];
    const float* xs  = (const float*)d_in[3];
    const float* xzp = (const float*)d_in[4];
    const float* ws  = (const float*)d_in[5];
    const float* wzp = (const float*)d_in[6];
    float* out = (float*)d_out;

    cudaFuncSetAttribute(lut_gemm_kernel,
                         cudaFuncAttributeMaxDynamicSharedMemorySize, SMEM_BYTES);

    quant_all_kernel<<<TOTROWS / 2, 256>>>(x, w, xs, xzp, ws, wzp);

    // GEMM with programmatic dependent launch (overlaps quant epilogue).
    cudaLaunchConfig_t cfg = {};
    cfg.gridDim  = dim3(MROWS / BM, KDIM / BN, 1);   // 32 x 4 = 128 blocks
    cfg.blockDim = dim3(512, 1, 1);
    cfg.dynamicSmemBytes = SMEM_BYTES;
    cfg.stream = 0;
    cudaLaunchAttribute attrs[1];
    attrs[0].id = cudaLaunchAttributeProgrammaticStreamSerialization;
    attrs[0].val.programmaticStreamSerializationAllowed = 1;
    cfg.attrs = attrs;
    cfg.numAttrs = 1;
    cudaLaunchKernelEx(&cfg, lut_gemm_kernel, out, xs, xzp, ws, wzp);
}

// round 6
// speedup vs baseline: 1.1032x; 1.1032x over previous
#include <cuda_runtime.h>
#include <cuda_bf16.h>
#include <cstdint>

// Problem shape (fixed)
#define MDIM 512            // reduction dim (bytes per int8 row)
#define KDIM 256            // output cols (w rows)
#define MROWS 2048          // output rows (B*N)
#define TOTROWS (MROWS + KDIM)

// GEMM tiling
#define BM 64
#define BN 32
#define A_TILE_BYTES (BM * MDIM)     // 32768
#define B_TILE_BYTES (BN * MDIM)     // 16384
#define SM_A_OFF 1024
#define SM_B_OFF (SM_A_OFF + A_TILE_BYTES)
#define SMEM_TOTAL (SM_B_OFF + B_TILE_BYTES)   // 50176

// Scratch: int8 operands stored with per-row chunk swizzle:
//   byte addr = row*512 + ((chunk ^ (row&7))<<4) + in-chunk offset
// This makes every GEMM tile a contiguous block whose smem image is
// directly ldmatrix-conflict-free (lanes r..r+7, same chunk -> 8 distinct
// 16B bank groups).
__device__ __align__(16) int8_t g_xq[MROWS * MDIM];   // 1 MB
__device__ __align__(16) int8_t g_wq[KDIM * MDIM];    // 128 KB
__device__ float g_rowsum[MROWS];
__device__ float g_colsum[KDIM];

// ---------------------------------------------------------------------------
// quantize: q = clip(rint(v/s + zp), -128, 127)
// ---------------------------------------------------------------------------
__device__ __forceinline__ float quantize1(float v, float s, float zp) {
    float q = rintf(__fadd_rn(__fdiv_rn(v, s), zp));
    return fminf(fmaxf(q, -128.0f), 127.0f);
}

// Fused quantize: rows [0,2048)=x, [2048,2304)=w. 2 rows/block, 4 warps/row.
// Stores int8 in the swizzled-chunk layout described above.
__global__ __launch_bounds__(256)
void quant_all_kernel(const float* __restrict__ x,
                      const float* __restrict__ w,
                      const float* __restrict__ xs_p, const float* __restrict__ xzp_p,
                      const float* __restrict__ ws_p, const float* __restrict__ wzp_p) {
    __shared__ float spart[8];
    const int tid  = threadIdx.x;
    const int lane = tid & 31;
    const int wid  = tid >> 5;
    const int row  = blockIdx.x * 2 + (tid >> 7);
    const int q4   = ((tid >> 5) & 3) * 32 + lane;   // float4 index in row (0..127)

    const bool isX = row < MROWS;
    const float s  = isX ? xs_p[0]  : ws_p[0];
    const float zp = isX ? xzp_p[0] : wzp_p[0];
    const int lrow = isX ? row : (row - MROWS);
    const float* src = isX ? (x + (size_t)lrow * MDIM)
                           : (w + (size_t)lrow * MDIM);
    int8_t* dstbase = isX ? (g_xq + (size_t)lrow * MDIM)
                          : (g_wq + (size_t)lrow * MDIM);

    float4 v = reinterpret_cast<const float4*>(src)[q4];
    float q0 = quantize1(v.x, s, zp);
    float q1 = quantize1(v.y, s, zp);
    float q2 = quantize1(v.z, s, zp);
    float q3 = quantize1(v.w, s, zp);

    int i0 = __float2int_rn(q0);
    int i1 = __float2int_rn(q1);
    int i2 = __float2int_rn(q2);
    int i3 = __float2int_rn(q3);
    uint32_t packed = (uint32_t)(i0 & 0xFF) | ((uint32_t)(i1 & 0xFF) << 8) |
                      ((uint32_t)(i2 & 0xFF) << 16) | ((uint32_t)i3 << 24);

    // swizzled store position: chunk c = q4>>2, word (q4&3) within chunk
    const int c  = q4 >> 2;
    const int sw = (c ^ (lrow & 7));
    *reinterpret_cast<uint32_t*>(dstbase + (sw << 4) + ((q4 & 3) << 2)) = packed;

    float sum = q0 + q1 + q2 + q3;
#pragma unroll
    for (int off = 16; off > 0; off >>= 1)
        sum += __shfl_xor_sync(0xFFFFFFFFu, sum, off);
    if (lane == 0) spart[wid] = sum;
    __syncthreads();
    if (tid < 2) {
        int r = blockIdx.x * 2 + tid;
        float total = spart[tid * 4 + 0] + spart[tid * 4 + 1] +
                      spart[tid * 4 + 2] + spart[tid * 4 + 3];
        if (r < MROWS) g_rowsum[r] = total;
        else           g_colsum[r - MROWS] = total;
    }
    asm volatile("griddepcontrol.launch_dependents;" ::: "memory");
}

// ---------------------------------------------------------------------------
// helpers
// ---------------------------------------------------------------------------
__device__ __forceinline__ uint32_t smem_u32(const void* p) {
    return (uint32_t)__cvta_generic_to_shared(p);
}
__device__ __forceinline__ void ldsm_x4(uint32_t& r0, uint32_t& r1,
                                        uint32_t& r2, uint32_t& r3, uint32_t addr) {
    asm volatile("ldmatrix.sync.aligned.m8n8.x4.shared.b16 {%0,%1,%2,%3}, [%4];"
                 : "=r"(r0), "=r"(r1), "=r"(r2), "=r"(r3) : "r"(addr));
}
__device__ __forceinline__ void imma16832(int& c0, int& c1, int& c2, int& c3,
                                          uint32_t a0, uint32_t a1, uint32_t a2, uint32_t a3,
                                          uint32_t b0, uint32_t b1) {
    asm volatile(
        "mma.sync.aligned.m16n8k32.row.col.s32.s8.s8.s32 "
        "{%0,%1,%2,%3}, {%4,%5,%6,%7}, {%8,%9}, {%0,%1,%2,%3};"
        : "+r"(c0), "+r"(c1), "+r"(c2), "+r"(c3)
        : "r"(a0), "r"(a1), "r"(a2), "r"(a3), "r"(b0), "r"(b1));
}

// ---------------------------------------------------------------------------
// GEMM: per CTA D[64,32] over full K=512, int8 IMMA.
// Tiles fetched with two 1D cp.async.bulk copies (contiguous in gmem thanks
// to the swizzled scratch layout). No syncs in the MMA loop.
// 128 threads, 4 warps (2m x 2n), warp tile 32x16, 4 IMMA chains per warp.
// ---------------------------------------------------------------------------
__global__ __launch_bounds__(128, 4)
void lut_gemm_kernel(float* __restrict__ out,
                     const float* __restrict__ xs_p, const float* __restrict__ xzp_p,
                     const float* __restrict__ ws_p, const float* __restrict__ wzp_p) {
    extern __shared__ int8_t smem[];
    const uint32_t sbase = smem_u32(smem);

    // PDL: quant grid's writes must be visible before we read g_xq/g_wq.
    asm volatile("griddepcontrol.wait;" ::: "memory");

    const int tid  = threadIdx.x;
    const int lane = tid & 31;
    const int warp = tid >> 5;
    const int wm = warp >> 1;       // 0..1 (32 rows)
    const int wn = warp & 1;        // 0..1 (16 cols)

    const int m0 = blockIdx.x * BM;
    const int n0 = blockIdx.y * BN;

    if (tid == 0) {
        asm volatile("mbarrier.init.shared.b64 [%0], %1;"
                     :: "r"(sbase), "r"(1u) : "memory");
    }
    __syncthreads();

    if (tid == 0) {
        asm volatile("mbarrier.arrive.expect_tx.shared.b64 _, [%0], %1;"
                     :: "r"(sbase), "r"((uint32_t)(A_TILE_BYTES + B_TILE_BYTES))
                     : "memory");
        asm volatile(
            "cp.async.bulk.shared::cluster.global.mbarrier::complete_tx::bytes "
            "[%0], [%1], %2, [%3];"
            :: "r"(sbase + SM_A_OFF), "l"(g_xq + (size_t)m0 * MDIM),
               "r"((uint32_t)A_TILE_BYTES), "r"(sbase) : "memory");
        asm volatile(
            "cp.async.bulk.shared::cluster.global.mbarrier::complete_tx::bytes "
            "[%0], [%1], %2, [%3];"
            :: "r"(sbase + SM_B_OFF), "l"(g_wq + (size_t)n0 * MDIM),
               "r"((uint32_t)B_TILE_BYTES), "r"(sbase) : "memory");
    }

    // wait for both bulk copies (phase 0)
    asm volatile(
        "{\n\t"
        ".reg .pred P1;\n\t"
        "WAIT_LOOP_%=:\n\t"
        "mbarrier.try_wait.parity.acquire.cta.shared::cta.b64 P1, [%0], 0, 0x989680;\n\t"
        "@P1 bra.uni WAIT_DONE_%=;\n\t"
        "bra.uni WAIT_LOOP_%=;\n\t"
        "WAIT_DONE_%=:\n\t"
        "}" :: "r"(sbase) : "memory");

    int acc[2][2][4];
#pragma unroll
    for (int mi = 0; mi < 2; mi++)
#pragma unroll
        for (int nb = 0; nb < 2; nb++)
#pragma unroll
            for (int q = 0; q < 4; q++) acc[mi][nb][q] = 0;

    // per-lane row indices (within tile) for ldmatrix
    const int a_r0 = wm * 32 + (lane & 7) + ((lane >> 3) & 1) * 8;  // + mi*16
    const int a_cb = (lane >> 4);                                    // chunk bit
    const int b_r  = wn * 16 + (lane & 7) + (lane >> 4) * 8;
    const int b_cb = ((lane >> 3) & 1);

    const uint32_t aBase = sbase + SM_A_OFF;
    const uint32_t bBase = sbase + SM_B_OFF;

#pragma unroll
    for (int ks = 0; ks < 16; ks++) {           // k32 per step
        const int cbase = ks * 2;               // 16B chunk index base
        uint32_t a[2][4];
#pragma unroll
        for (int mi = 0; mi < 2; mi++) {
            int r = a_r0 + mi * 16;
            int c = (cbase + a_cb) ^ (r & 7);
            ldsm_x4(a[mi][0], a[mi][1], a[mi][2], a[mi][3],
                    aBase + r * MDIM + (c << 4));
        }
        uint32_t b0, b1, b2, b3;
        {
            int c = (cbase + b_cb) ^ (b_r & 7);
            ldsm_x4(b0, b1, b2, b3, bBase + b_r * MDIM + (c << 4));
        }
#pragma unroll
        for (int mi = 0; mi < 2; mi++) {
            imma16832(acc[mi][0][0], acc[mi][0][1], acc[mi][0][2], acc[mi][0][3],
                      a[mi][0], a[mi][1], a[mi][2], a[mi][3], b0, b1);
            imma16832(acc[mi][1][0], acc[mi][1][1], acc[mi][1][2], acc[mi][1][3],
                      a[mi][0], a[mi][1], a[mi][2], a[mi][3], b2, b3);
        }
    }

    // ---- epilogue: zero-point corrections + rescale (exact in fp32) ----
    const float xs  = xs_p[0];
    const float xzp = xzp_p[0];
    const float ws  = ws_p[0];
    const float wzp = wzp_p[0];
    const float sc  = xs * ws;
    const float kconst = (float)MDIM * xzp * wzp;

#pragma unroll
    for (int mi = 0; mi < 2; mi++) {
#pragma unroll
        for (int nb = 0; nb < 2; nb++) {
            int col = n0 + wn * 16 + nb * 8 + (lane & 3) * 2;
            float cs0 = g_colsum[col];
            float cs1 = g_colsum[col + 1];
#pragma unroll
            for (int half = 0; half < 2; half++) {
                int row = m0 + wm * 32 + mi * 16 + (lane >> 2) + half * 8;
                float rs = g_rowsum[row];
                float corr = kconst - wzp * rs;
                float v0 = (__int2float_rn(acc[mi][nb][half * 2 + 0]) + corr - xzp * cs0) * sc;
                float v1 = (__int2float_rn(acc[mi][nb][half * 2 + 1]) + corr - xzp * cs1) * sc;
                *reinterpret_cast<float2*>(out + (size_t)row * KDIM + col) =
                    make_float2(v0, v1);
            }
        }
    }
}

// ---------------------------------------------------------------------------
// Launch. Inputs: x, w, lut, x_scale, x_zero_point, w_scale, w_zero_point.
// ---------------------------------------------------------------------------
extern "C" void kernel_launch(void* const* d_in, const int* in_sizes, int n_in,
                              void* d_out, int out_size) {
    const float* x   = (const float*)d_in[0];
    const float* w   = (const float*)d_in[1];
    const float* xs  = (const float*)d_in[3];
    const float* xzp = (const float*)d_in[4];
    const float* ws  = (const float*)d_in[5];
    const float* wzp = (const float*)d_in[6];
    float* out = (float*)d_out;

    cudaFuncSetAttribute(lut_gemm_kernel,
                         cudaFuncAttributeMaxDynamicSharedMemorySize, SMEM_TOTAL);

    quant_all_kernel<<<TOTROWS / 2, 256>>>(x, w, xs, xzp, ws, wzp);

    // GEMM with programmatic dependent launch (overlaps quant tail).
    cudaLaunchConfig_t cfg = {};
    cfg.gridDim  = dim3(MROWS / BM, KDIM / BN, 1);   // 32 x 8 = 256 CTAs
    cfg.blockDim = dim3(128, 1, 1);
    cfg.dynamicSmemBytes = SMEM_TOTAL;
    cfg.stream = 0;
    cudaLaunchAttribute attrs[1];
    attrs[0].id = cudaLaunchAttributeProgrammaticStreamSerialization;
    attrs[0].val.programmaticStreamSerializationAllowed = 1;
    cfg.attrs = attrs;
    cfg.numAttrs = 1;
    cudaLaunchKernelEx(&cfg, lut_gemm_kernel, out, xs, xzp, ws, wzp);
}

// round 7
// speedup vs baseline: 1.3090x; 1.1866x over previous
#include <cuda_runtime.h>
#include <cuda_bf16.h>
#include <cstdint>

// Problem shape (fixed)
#define MDIM 512            // reduction dim
#define KDIM 256            // output cols (w rows)
#define MROWS 2048          // output rows (B*N)
#define TOTROWS (MROWS + KDIM)

#define NSLICE 4            // K slices of 128
#define SLICE_K 128         // bf16 elems per slice per row
#define SLICE_ROWB 256      // bytes per row per slice (128 bf16)

// GEMM tiling
#define BM 64
#define BN 32
#define A_SL_BYTES (BM * SLICE_ROWB)   // 16384
#define B_SL_BYTES (BN * SLICE_ROWB)   // 8192
#define STG_BYTES (A_SL_BYTES + B_SL_BYTES)  // 24576
#define SM_DATA_OFF 1024
#define SMEM_TOTAL (SM_DATA_OFF + NSLICE * STG_BYTES)   // 99328

// Scratch: bf16 operands, SLICE-MAJOR with per-row chunk swizzle.
//   addr(elem row r, slice s, chunk c(16B), half h(8B)) =
//     (s*NROWS + r)*256 + ((c ^ (r&7))<<4) + h*8
// Every (64-row, slice) A block and (32-row, slice) B block is contiguous.
__device__ __align__(16) __nv_bfloat16 g_xq[MROWS * MDIM];   // 2 MB
__device__ __align__(16) __nv_bfloat16 g_wq[KDIM * MDIM];    // 256 KB
__device__ float g_rowsum[MROWS];
__device__ float g_colsum[KDIM];

// ---------------------------------------------------------------------------
__device__ __forceinline__ float quantize1(float v, float s, float zp) {
    float q = rintf(__fadd_rn(__fdiv_rn(v, s), zp));
    return fminf(fmaxf(q, -128.0f), 127.0f);
}

// Fused quantize: rows [0,2048)=x, [2048,2304)=w. 2 rows/block, 4 warps/row.
__global__ __launch_bounds__(256)
void quant_all_kernel(const float* __restrict__ x,
                      const float* __restrict__ w,
                      const float* __restrict__ xs_p, const float* __restrict__ xzp_p,
                      const float* __restrict__ ws_p, const float* __restrict__ wzp_p) {
    __shared__ float spart[8];
    const int tid  = threadIdx.x;
    const int lane = tid & 31;
    const int wid  = tid >> 5;
    const int row  = blockIdx.x * 2 + (tid >> 7);
    const int q4   = ((tid >> 5) & 3) * 32 + lane;   // float4 index (0..127)

    const bool isX = row < MROWS;
    const float s  = isX ? xs_p[0]  : ws_p[0];
    const float zp = isX ? xzp_p[0] : wzp_p[0];
    const int lrow = isX ? row : (row - MROWS);
    const int nrows = isX ? MROWS : KDIM;
    const float* src = isX ? (x + (size_t)lrow * MDIM)
                           : (w + (size_t)lrow * MDIM);
    int8_t* base = isX ? reinterpret_cast<int8_t*>(g_xq)
                       : reinterpret_cast<int8_t*>(g_wq);

    float4 v = reinterpret_cast<const float4*>(src)[q4];
    float q0 = quantize1(v.x, s, zp);
    float q1 = quantize1(v.y, s, zp);
    float q2 = quantize1(v.z, s, zp);
    float q3 = quantize1(v.w, s, zp);
    __nv_bfloat162 p01 = __floats2bfloat162_rn(q0, q1);
    __nv_bfloat162 p23 = __floats2bfloat162_rn(q2, q3);
    uint2 packed;
    packed.x = *reinterpret_cast<uint32_t*>(&p01);
    packed.y = *reinterpret_cast<uint32_t*>(&p23);

    // slice-major swizzled store (8 bytes per thread)
    const int sl = q4 >> 5;                 // slice (32 float4 = 128 elems)
    const int c  = (q4 & 31) >> 1;          // 16B chunk within slice row (0..15)
    const int h  = q4 & 1;                  // 8B half within chunk
    size_t off = ((size_t)sl * nrows + lrow) * SLICE_ROWB
               + (size_t)(((c ^ (lrow & 7)) << 4) + h * 8);
    *reinterpret_cast<uint2*>(base + off) = packed;

    float sum = q0 + q1 + q2 + q3;
#pragma unroll
    for (int off2 = 16; off2 > 0; off2 >>= 1)
        sum += __shfl_xor_sync(0xFFFFFFFFu, sum, off2);
    if (lane == 0) spart[wid] = sum;
    __syncthreads();
    if (tid < 2) {
        int r = blockIdx.x * 2 + tid;
        float total = spart[tid * 4 + 0] + spart[tid * 4 + 1] +
                      spart[tid * 4 + 2] + spart[tid * 4 + 3];
        if (r < MROWS) g_rowsum[r] = total;
        else           g_colsum[r - MROWS] = total;
    }
    asm volatile("griddepcontrol.launch_dependents;" ::: "memory");
}

// ---------------------------------------------------------------------------
// helpers
// ---------------------------------------------------------------------------
__device__ __forceinline__ uint32_t smem_u32(const void* p) {
    return (uint32_t)__cvta_generic_to_shared(p);
}
__device__ __forceinline__ void ldsm_x4(uint32_t& r0, uint32_t& r1,
                                        uint32_t& r2, uint32_t& r3, uint32_t addr) {
    asm volatile("ldmatrix.sync.aligned.m8n8.x4.shared.b16 {%0,%1,%2,%3}, [%4];"
                 : "=r"(r0), "=r"(r1), "=r"(r2), "=r"(r3) : "r"(addr));
}
__device__ __forceinline__ void mma16816(float& c0, float& c1, float& c2, float& c3,
                                         uint32_t a0, uint32_t a1, uint32_t a2, uint32_t a3,
                                         uint32_t b0, uint32_t b1) {
    asm volatile(
        "mma.sync.aligned.m16n8k16.row.col.f32.bf16.bf16.f32 "
        "{%0,%1,%2,%3}, {%4,%5,%6,%7}, {%8,%9}, {%0,%1,%2,%3};"
        : "+f"(c0), "+f"(c1), "+f"(c2), "+f"(c3)
        : "r"(a0), "r"(a1), "r"(a2), "r"(a3), "r"(b0), "r"(b1));
}
__device__ __forceinline__ void bulk_copy(uint32_t sdst, const void* gsrc,
                                          uint32_t bytes, uint32_t mbar) {
    asm volatile(
        "cp.async.bulk.shared::cluster.global.mbarrier::complete_tx::bytes "
        "[%0], [%1], %2, [%3];"
        :: "r"(sdst), "l"(gsrc), "r"(bytes), "r"(mbar) : "memory");
}
__device__ __forceinline__ void mbar_wait0(uint32_t mbar) {
    asm volatile(
        "{\n\t"
        ".reg .pred P1;\n\t"
        "WAIT_LOOP_%=:\n\t"
        "mbarrier.try_wait.parity.acquire.cta.shared::cta.b64 P1, [%0], 0, 0x989680;\n\t"
        "@P1 bra.uni WAIT_DONE_%=;\n\t"
        "bra.uni WAIT_LOOP_%=;\n\t"
        "WAIT_DONE_%=:\n\t"
        "}" :: "r"(mbar) : "memory");
}

// ---------------------------------------------------------------------------
// GEMM: per CTA D[64,32] over K=512, bf16 HMMA (exact int math).
// 4 K-slices, each fetched as two contiguous cp.async.bulk copies.
// All bulks issued up front; per-slice mbarrier waits; no __syncthreads in loop.
// 128 threads, 4 warps (2m x 2n), warp tile 32x16.
// ---------------------------------------------------------------------------
__global__ __launch_bounds__(128, 2)
void lut_gemm_kernel(float* __restrict__ out,
                     const float* __restrict__ xs_p, const float* __restrict__ xzp_p,
                     const float* __restrict__ ws_p, const float* __restrict__ wzp_p) {
    extern __shared__ int8_t smem[];
    const uint32_t sbase = smem_u32(smem);

    // PDL: quant grid's writes must be visible before reading g_xq/g_wq.
    asm volatile("griddepcontrol.wait;" ::: "memory");

    const int tid  = threadIdx.x;
    const int lane = tid & 31;
    const int warp = tid >> 5;
    const int wm = warp >> 1;       // 0..1 (32 rows)
    const int wn = warp & 1;        // 0..1 (16 cols)

    const int m0 = blockIdx.x * BM;
    const int n0 = blockIdx.y * BN;

    if (tid == 0) {
#pragma unroll
        for (int s = 0; s < NSLICE; s++)
            asm volatile("mbarrier.init.shared.b64 [%0], %1;"
                         :: "r"(sbase + s * 8), "r"(1u) : "memory");
    }
    __syncthreads();

    if (tid == 0) {
#pragma unroll
        for (int s = 0; s < NSLICE; s++) {
            uint32_t mbar = sbase + s * 8;
            asm volatile("mbarrier.arrive.expect_tx.shared.b64 _, [%0], %1;"
                         :: "r"(mbar), "r"((uint32_t)STG_BYTES) : "memory");
            const int8_t* asrc = reinterpret_cast<const int8_t*>(g_xq)
                + ((size_t)s * MROWS + m0) * SLICE_ROWB;
            const int8_t* bsrc = reinterpret_cast<const int8_t*>(g_wq)
                + ((size_t)s * KDIM + n0) * SLICE_ROWB;
            uint32_t sA = sbase + SM_DATA_OFF + s * STG_BYTES;
            bulk_copy(sA, asrc, A_SL_BYTES, mbar);
            bulk_copy(sA + A_SL_BYTES, bsrc, B_SL_BYTES, mbar);
        }
    }

    float acc[2][2][4];
#pragma unroll
    for (int mi = 0; mi < 2; mi++)
#pragma unroll
        for (int ni = 0; ni < 2; ni++)
#pragma unroll
            for (int q = 0; q < 4; q++) acc[mi][ni][q] = 0.0f;

    // lane addressing (validated mappings from round 3)
    const int a_r0 = wm * 32 + (lane & 15);     // + mi*16
    const int a_cb = lane >> 4;                 // A chunk bit (k half)
    const int b_r  = wn * 16 + (lane >> 4) * 8 + (lane & 7);
    const int b_cb = (lane >> 3) & 1;           // B chunk bit (k half)

#pragma unroll
    for (int s = 0; s < NSLICE; s++) {
        mbar_wait0(sbase + s * 8);
        const uint32_t aSl = sbase + SM_DATA_OFF + s * STG_BYTES;
        const uint32_t bSl = aSl + A_SL_BYTES;

#pragma unroll
        for (int ks = 0; ks < SLICE_K / 16; ks++) {   // 8 k16 steps
            const int cbase = ks * 2;                 // chunk pair base
            uint32_t a[2][4];
#pragma unroll
            for (int mi = 0; mi < 2; mi++) {
                int r = a_r0 + mi * 16;
                int c = (cbase + a_cb) ^ (r & 7);
                ldsm_x4(a[mi][0], a[mi][1], a[mi][2], a[mi][3],
                        aSl + r * SLICE_ROWB + (c << 4));
            }
            uint32_t b0, b1, b2, b3;
            {
                int c = (cbase + b_cb) ^ (b_r & 7);
                ldsm_x4(b0, b1, b2, b3, bSl + b_r * SLICE_ROWB + (c << 4));
            }
#pragma unroll
            for (int mi = 0; mi < 2; mi++) {
                mma16816(acc[mi][0][0], acc[mi][0][1], acc[mi][0][2], acc[mi][0][3],
                         a[mi][0], a[mi][1], a[mi][2], a[mi][3], b0, b1);
                mma16816(acc[mi][1][0], acc[mi][1][1], acc[mi][1][2], acc[mi][1][3],
                         a[mi][0], a[mi][1], a[mi][2], a[mi][3], b2, b3);
            }
        }
    }

    // ---- epilogue: zero-point corrections + rescale ----
    const float xs  = xs_p[0];
    const float xzp = xzp_p[0];
    const float ws  = ws_p[0];
    const float wzp = wzp_p[0];
    const float sc  = xs * ws;
    const float kconst = (float)MDIM * xzp * wzp;

#pragma unroll
    for (int mi = 0; mi < 2; mi++) {
#pragma unroll
        for (int ni = 0; ni < 2; ni++) {
            int col = n0 + wn * 16 + ni * 8 + (lane & 3) * 2;
            float cs0 = g_colsum[col];
            float cs1 = g_colsum[col + 1];
#pragma unroll
            for (int half = 0; half < 2; half++) {
                int row = m0 + wm * 32 + mi * 16 + (lane >> 2) + half * 8;
                float rs = g_rowsum[row];
                float corr = kconst - wzp * rs;
                float v0 = (acc[mi][ni][half * 2 + 0] + corr - xzp * cs0) * sc;
                float v1 = (acc[mi][ni][half * 2 + 1] + corr - xzp * cs1) * sc;
                *reinterpret_cast<float2*>(out + (size_t)row * KDIM + col) =
                    make_float2(v0, v1);
            }
        }
    }
}

// ---------------------------------------------------------------------------
// Launch. Inputs: x, w, lut, x_scale, x_zero_point, w_scale, w_zero_point.
// ---------------------------------------------------------------------------
extern "C" void kernel_launch(void* const* d_in, const int* in_sizes, int n_in,
                              void* d_out, int out_size) {
    const float* x   = (const float*)d_in[0];
    const float* w   = (const float*)d_in[1];
    const float* xs  = (const float*)d_in[3];
    const float* xzp = (const float*)d_in[4];
    const float* ws  = (const float*)d_in[5];
    const float* wzp = (const float*)d_in[6];
    float* out = (float*)d_out;

    cudaFuncSetAttribute(lut_gemm_kernel,
                         cudaFuncAttributeMaxDynamicSharedMemorySize, SMEM_TOTAL);

    quant_all_kernel<<<TOTROWS / 2, 256>>>(x, w, xs, xzp, ws, wzp);

    cudaLaunchConfig_t cfg = {};
    cfg.gridDim  = dim3(MROWS / BM, KDIM / BN, 1);   // 32 x 8 = 256 CTAs
    cfg.blockDim = dim3(128, 1, 1);
    cfg.dynamicSmemBytes = SMEM_TOTAL;
    cfg.stream = 0;
    cudaLaunchAttribute attrs[1];
    attrs[0].id = cudaLaunchAttributeProgrammaticStreamSerialization;
    attrs[0].val.programmaticStreamSerializationAllowed = 1;
    cfg.attrs = attrs;
    cfg.numAttrs = 1;
    cudaLaunchKernelEx(&cfg, lut_gemm_kernel, out, xs, xzp, ws, wzp);
}